// round 2
// baseline (speedup 1.0000x reference)
#include <cuda_runtime.h>
#include <cstdint>

// ============================================================================
// out[16384,1024] = (W0[idx] @ W1) * (idx != 0) * 32.0
//   d_in[0] inputs: int32 [4,4096] -> 16384 tokens
//   d_in[1] W0:     fp32 [32000, 2048]
//   d_in[2] W1:     fp32 [2048, 1024]
//
// compute_100 virtual arch rejects tcgen05 => use sm_80 path:
//   cp.async 4-stage pipeline + ldmatrix.b16 + mma.sync.m16n8k8.tf32.
// W1 is transposed to [1024,2048] (K-major) and tf32-rounded (cvt.rna) by a
// prep kernel; A fragments are tf32-rounded after ldmatrix (unbiased rounding
// keeps norm rel-err ~4e-4).
// ============================================================================

namespace {

constexpr int TOKENS = 16384;
constexpr int KDIM   = 2048;
constexpr int HDIM   = 1024;

constexpr int BM = 128;
constexpr int BN = 256;
constexpr int BK = 32;              // 32 fp32 = 128 B rows
constexpr int STAGES = 4;
constexpr int KITERS = KDIM / BK;   // 64

constexpr int THREADS = 256;        // 8 warps: 2 (M) x 4 (N), warp tile 64x64

constexpr uint32_t A_STAGE_BYTES = BM * 128;              // 16 KB
constexpr uint32_t B_STAGE_BYTES = BN * 128;              // 32 KB
constexpr uint32_t STAGE_BYTES   = A_STAGE_BYTES + B_STAGE_BYTES;  // 48 KB
constexpr uint32_t SMEM_TOTAL    = STAGES * STAGE_BYTES;  // 192 KB

__device__ float g_Wt[HDIM * KDIM];   // W1^T, K-major, tf32-rounded

// ---------------------------------------------------------------------------
// helpers
// ---------------------------------------------------------------------------
__device__ __forceinline__ uint32_t smem_u32(const void* p) {
    uint32_t a;
    asm("{ .reg .u64 t; cvta.to.shared.u64 t, %1; cvt.u32.u64 %0, t; }"
        : "=r"(a) : "l"(p));
    return a;
}

#define CP_ASYNC16(dst, src) \
    asm volatile("cp.async.cg.shared.global [%0], [%1], 16;" \
                 :: "r"(dst), "l"(src) : "memory")
#define CP_COMMIT() asm volatile("cp.async.commit_group;" ::: "memory")
#define CP_WAIT(n)  asm volatile("cp.async.wait_group %0;" :: "n"(n) : "memory")

#define LDMX4(r, addr)                                                        \
    asm volatile("ldmatrix.sync.aligned.m8n8.x4.shared.b16 {%0,%1,%2,%3}, [%4];" \
        : "=r"((r)[0]), "=r"((r)[1]), "=r"((r)[2]), "=r"((r)[3])              \
        : "r"(addr))

__device__ __forceinline__ uint32_t f2tf32(uint32_t x) {
    uint32_t y;
    float fx = __uint_as_float(x);
    asm("cvt.rna.tf32.f32 %0, %1;" : "=r"(y) : "f"(fx));
    return y;
}

__device__ __forceinline__ void mma_tf32(float* d, const uint32_t* a,
                                         const uint32_t* b) {
    asm volatile(
        "mma.sync.aligned.m16n8k8.row.col.f32.tf32.tf32.f32 "
        "{%0,%1,%2,%3}, {%4,%5,%6,%7}, {%8,%9}, {%0,%1,%2,%3};"
        : "+f"(d[0]), "+f"(d[1]), "+f"(d[2]), "+f"(d[3])
        : "r"(a[0]), "r"(a[1]), "r"(a[2]), "r"(a[3]), "r"(b[0]), "r"(b[1]));
}

// ---------------------------------------------------------------------------
// prep: W1 [2048,1024] -> g_Wt [1024,2048] K-major, tf32-rounded
// ---------------------------------------------------------------------------
__global__ void transpose_w1(const float* __restrict__ W1) {
    __shared__ float tile[32][33];
    int n0 = blockIdx.x * 32;
    int k0 = blockIdx.y * 32;
    int tx = threadIdx.x;
#pragma unroll
    for (int dy = 0; dy < 32; dy += 8) {
        int ty = threadIdx.y + dy;
        tile[ty][tx] = W1[(size_t)(k0 + ty) * HDIM + n0 + tx];
    }
    __syncthreads();
#pragma unroll
    for (int dy = 0; dy < 32; dy += 8) {
        int ty = threadIdx.y + dy;
        float v = tile[tx][ty];
        g_Wt[(size_t)(n0 + ty) * KDIM + k0 + tx] =
            __uint_as_float(f2tf32(__float_as_uint(v)));
    }
}

// ---------------------------------------------------------------------------
// main gather-GEMM
// ---------------------------------------------------------------------------
__global__ __launch_bounds__(THREADS, 1)
void gather_gemm_tf32(const int* __restrict__ inputs,
                      const float* __restrict__ W0,
                      float* __restrict__ out) {
    extern __shared__ char smem[];
    const uint32_t smem_base = smem_u32(smem);

    const int tid  = threadIdx.x;
    const int lane = tid & 31;
    const int wid  = tid >> 5;

    const int mtile  = blockIdx.x >> 2;   // 0..127
    const int ntile  = blockIdx.x & 3;    // 0..3
    const int m_base = mtile * BM;
    const int n_base = ntile * BN;

    // ---- staging parameters (all threads stage) ----
    // A: thread t stages row t/2, chunks (t&1)*4 .. +3 (64 contiguous bytes)
    const int arow    = tid >> 1;
    const int achunk0 = (tid & 1) * 4;
    const int tokA    = inputs[m_base + arow];
    const float* aSrc = W0 + (size_t)tokA * KDIM + achunk0 * 4;
    const uint32_t aDstBase = smem_base + (uint32_t)arow * 128u;
    const uint32_t aSw = (uint32_t)(arow & 7);
    // B: thread t stages n-row t (8 chunks = full 128B row)
    const float* bSrc = g_Wt + (size_t)(n_base + tid) * KDIM;
    const uint32_t bDstBase = smem_base + A_STAGE_BYTES + (uint32_t)tid * 128u;
    const uint32_t bSw = (uint32_t)(tid & 7);

    // ---- fragment ldmatrix parameters ----
    const int wm = (wid & 1) * 64;   // warp M offset
    const int wn = (wid >> 1) * 64;  // warp N offset
    // A: matrices 0/1 = rows base+0..7 / +8..15 at chunk 2ks;
    //    matrices 2/3 = same rows at chunk 2ks+1.
    const int arF  = (lane & 7) + (((lane >> 3) & 1) << 3);
    const uint32_t acp  = (uint32_t)((lane >> 4) & 1);
    const uint32_t as7  = (uint32_t)(lane & 7);
    uint32_t rowA[4];
#pragma unroll
    for (int mt = 0; mt < 4; mt++)
        rowA[mt] = smem_base + (uint32_t)(wm + 16 * mt + arF) * 128u;
    // B: matrices 0/1 = n-rows base+0..7, chunks 2ks / 2ks+1;
    //    matrices 2/3 = n-rows base+8..15, chunks 2ks / 2ks+1.
    const int brF  = (lane & 7) + (((lane >> 4) & 1) << 3);
    const uint32_t bcp  = (uint32_t)((lane >> 3) & 1);
    const uint32_t bs7  = (uint32_t)(lane & 7);
    uint32_t rowB[4];
#pragma unroll
    for (int gg = 0; gg < 4; gg++)
        rowB[gg] = smem_base + A_STAGE_BYTES +
                   (uint32_t)(wn + 16 * gg + brF) * 128u;

    float acc[4][8][4];
#pragma unroll
    for (int mt = 0; mt < 4; mt++)
#pragma unroll
        for (int nt = 0; nt < 8; nt++)
#pragma unroll
            for (int i = 0; i < 4; i++) acc[mt][nt][i] = 0.0f;

    // ---- stage issue ----
    auto issue = [&](int kt) {
        const uint32_t stage = (uint32_t)(kt & (STAGES - 1)) * STAGE_BYTES;
        const float* as = aSrc + kt * BK;
#pragma unroll
        for (int j = 0; j < 4; j++) {
            CP_ASYNC16(aDstBase + stage +
                           ((((uint32_t)(achunk0 + j)) ^ aSw) * 16u),
                       as + j * 4);
        }
        const float* bs = bSrc + kt * BK;
#pragma unroll
        for (int j = 0; j < 8; j++) {
            CP_ASYNC16(bDstBase + stage + ((((uint32_t)j) ^ bSw) * 16u),
                       bs + j * 4);
        }
    };

    // prologue: tiles 0..STAGES-2
#pragma unroll
    for (int p = 0; p < STAGES - 1; p++) {
        issue(p);
        CP_COMMIT();
    }

    // ---- main loop ----
    for (int kt = 0; kt < KITERS; kt++) {
        CP_WAIT(STAGES - 2);
        __syncthreads();

        if (kt + STAGES - 1 < KITERS) issue(kt + STAGES - 1);
        CP_COMMIT();

        const uint32_t stage = (uint32_t)(kt & (STAGES - 1)) * STAGE_BYTES;

#pragma unroll
        for (int ks = 0; ks < 4; ks++) {
            const uint32_t ak = (((uint32_t)(2 * ks) + acp) ^ as7) * 16u + stage;
            const uint32_t bk = (((uint32_t)(2 * ks) + bcp) ^ bs7) * 16u + stage;

            uint32_t a[4][4];
#pragma unroll
            for (int mt = 0; mt < 4; mt++) {
                LDMX4(a[mt], rowA[mt] + ak);
#pragma unroll
                for (int i = 0; i < 4; i++) a[mt][i] = f2tf32(a[mt][i]);
            }
            uint32_t b[4][4];   // [gg][0..1]=tile 2gg b0,b1; [2..3]=tile 2gg+1
#pragma unroll
            for (int gg = 0; gg < 4; gg++) LDMX4(b[gg], rowB[gg] + bk);

#pragma unroll
            for (int mt = 0; mt < 4; mt++)
#pragma unroll
                for (int nt = 0; nt < 8; nt++)
                    mma_tf32(acc[mt][nt], a[mt], &b[nt >> 1][(nt & 1) * 2]);
        }
    }

    // ---- epilogue: mask * 32, direct STG.64 ----
#pragma unroll
    for (int mt = 0; mt < 4; mt++) {
        const int r0 = m_base + wm + 16 * mt + (lane >> 2);
        const int r1 = r0 + 8;
        const float s0 = (inputs[r0] != 0) ? 32.0f : 0.0f;
        const float s1 = (inputs[r1] != 0) ? 32.0f : 0.0f;
        float* o0 = out + (size_t)r0 * HDIM + n_base + wn + 2 * (lane & 3);
        float* o1 = out + (size_t)r1 * HDIM + n_base + wn + 2 * (lane & 3);
#pragma unroll
        for (int nt = 0; nt < 8; nt++) {
            float2 v0 = make_float2(acc[mt][nt][0] * s0, acc[mt][nt][1] * s0);
            float2 v1 = make_float2(acc[mt][nt][2] * s1, acc[mt][nt][3] * s1);
            *reinterpret_cast<float2*>(o0 + nt * 8) = v0;
            *reinterpret_cast<float2*>(o1 + nt * 8) = v1;
        }
    }
}

}  // anonymous namespace

// ---------------------------------------------------------------------------
extern "C" void kernel_launch(void* const* d_in, const int* in_sizes, int n_in,
                              void* d_out, int out_size) {
    const int*   inputs = (const int*)d_in[0];
    const float* W0     = (const float*)d_in[1];
    const float* W1     = (const float*)d_in[2];
    float*       out    = (float*)d_out;
    (void)in_sizes; (void)n_in; (void)out_size;

    cudaFuncSetAttribute(gather_gemm_tf32,
                         cudaFuncAttributeMaxDynamicSharedMemorySize,
                         SMEM_TOTAL);

    transpose_w1<<<dim3(HDIM / 32, KDIM / 32), dim3(32, 8)>>>(W1);

    const int grid = (TOKENS / BM) * (HDIM / BN);   // 128 * 4 = 512
    gather_gemm_tf32<<<grid, THREADS, SMEM_TOTAL>>>(inputs, W0, out);
}

// round 3
// speedup vs baseline: 2.7922x; 2.7922x over previous
#include <cuda_runtime.h>
#include <cuda_fp16.h>
#include <cstdint>

// ============================================================================
// out[16384,1024] = (W0[idx] @ W1) * (idx != 0) * 32.0
//
// Round 3 strategy (compute_100 virtual arch: no tcgen05, sm_80 mma path):
//   prep_a: gather W0 rows -> dense fp16 A16[16384,2048], folding in
//           mask (token==0 -> 0) and the *32 scale (exact in fp16).
//   prep_b: W1 -> W1^T fp16 [1024,2048] (K-major).
//   main:   dense fp16 GEMM, mma.m16n8k16.f16 (2x K and >=2x rate vs tf32),
//           512 threads (16 warps) for 2x occupancy, 4-stage cp.async.
// fp16 mantissa == tf32 mantissa -> same ~3e-4 rel_err as the passing run.
// ============================================================================

namespace {

constexpr int TOKENS = 16384;
constexpr int KDIM   = 2048;
constexpr int HDIM   = 1024;

constexpr int BM = 128;
constexpr int BN = 256;
constexpr int BK = 64;              // 64 halfs = 128 B rows
constexpr int STAGES = 4;
constexpr int KITERS = KDIM / BK;   // 32

constexpr int THREADS = 512;        // 16 warps: 2 (M) x 8 (N), warp tile 64x32

constexpr uint32_t A_STAGE_BYTES = BM * 128;                       // 16 KB
constexpr uint32_t B_STAGE_BYTES = BN * 128;                       // 32 KB
constexpr uint32_t STAGE_BYTES   = A_STAGE_BYTES + B_STAGE_BYTES;  // 48 KB
constexpr uint32_t SMEM_TOTAL    = STAGES * STAGE_BYTES;           // 192 KB

__device__ __half g_A16[(size_t)TOKENS * KDIM];  // gathered, masked, *32
__device__ __half g_Bt[(size_t)HDIM * KDIM];     // W1^T, K-major

// ---------------------------------------------------------------------------
// helpers
// ---------------------------------------------------------------------------
__device__ __forceinline__ uint32_t smem_u32(const void* p) {
    uint32_t a;
    asm("{ .reg .u64 t; cvta.to.shared.u64 t, %1; cvt.u32.u64 %0, t; }"
        : "=r"(a) : "l"(p));
    return a;
}

#define CP_ASYNC16(dst, src) \
    asm volatile("cp.async.cg.shared.global [%0], [%1], 16;" \
                 :: "r"(dst), "l"(src) : "memory")
#define CP_COMMIT() asm volatile("cp.async.commit_group;" ::: "memory")
#define CP_WAIT(n)  asm volatile("cp.async.wait_group %0;" :: "n"(n) : "memory")

#define LDMX4(r, addr)                                                        \
    asm volatile("ldmatrix.sync.aligned.m8n8.x4.shared.b16 {%0,%1,%2,%3}, [%4];" \
        : "=r"((r)[0]), "=r"((r)[1]), "=r"((r)[2]), "=r"((r)[3])              \
        : "r"(addr))

__device__ __forceinline__ void mma_f16(float* d, const uint32_t* a,
                                        const uint32_t* b) {
    asm volatile(
        "mma.sync.aligned.m16n8k16.row.col.f32.f16.f16.f32 "
        "{%0,%1,%2,%3}, {%4,%5,%6,%7}, {%8,%9}, {%0,%1,%2,%3};"
        : "+f"(d[0]), "+f"(d[1]), "+f"(d[2]), "+f"(d[3])
        : "r"(a[0]), "r"(a[1]), "r"(a[2]), "r"(a[3]), "r"(b[0]), "r"(b[1]));
}

// ---------------------------------------------------------------------------
// prep_a: A16[row] = half(W0[inputs[row]] * (inputs[row] ? 32 : 0))
// ---------------------------------------------------------------------------
__global__ __launch_bounds__(256)
void prep_a(const int* __restrict__ inputs, const float* __restrict__ W0) {
    const int row = blockIdx.x;
    const int tok = inputs[row];
    const float sc = (tok != 0) ? 32.0f : 0.0f;
    const float4* src =
        reinterpret_cast<const float4*>(W0 + (size_t)tok * KDIM);
    uint2* dst = reinterpret_cast<uint2*>(g_A16 + (size_t)row * KDIM);
#pragma unroll 2
    for (int i = threadIdx.x; i < KDIM / 4; i += 256) {
        float4 v = src[i];
        __half2 h0 = __floats2half2_rn(v.x * sc, v.y * sc);
        __half2 h1 = __floats2half2_rn(v.z * sc, v.w * sc);
        uint2 u;
        u.x = *reinterpret_cast<uint32_t*>(&h0);
        u.y = *reinterpret_cast<uint32_t*>(&h1);
        dst[i] = u;
    }
}

// ---------------------------------------------------------------------------
// prep_b: W1 [2048,1024] -> g_Bt [1024,2048] K-major fp16
// ---------------------------------------------------------------------------
__global__ void prep_b(const float* __restrict__ W1) {
    __shared__ float tile[32][33];
    int n0 = blockIdx.x * 32;
    int k0 = blockIdx.y * 32;
    int tx = threadIdx.x;
#pragma unroll
    for (int dy = 0; dy < 32; dy += 8) {
        int ty = threadIdx.y + dy;
        tile[ty][tx] = W1[(size_t)(k0 + ty) * HDIM + n0 + tx];
    }
    __syncthreads();
#pragma unroll
    for (int dy = 0; dy < 32; dy += 8) {
        int ty = threadIdx.y + dy;
        g_Bt[(size_t)(n0 + ty) * KDIM + k0 + tx] = __float2half_rn(tile[tx][ty]);
    }
}

// ---------------------------------------------------------------------------
// main dense fp16 GEMM: out[16384,1024] = A16 @ Bt^T   (fp32 accumulate)
// ---------------------------------------------------------------------------
__global__ __launch_bounds__(THREADS, 1)
void gemm_f16(float* __restrict__ out) {
    extern __shared__ char smem[];
    const uint32_t smem_base = smem_u32(smem);

    const int tid  = threadIdx.x;
    const int lane = tid & 31;
    const int wid  = tid >> 5;

    const int mtile  = blockIdx.x >> 2;   // 0..127
    const int ntile  = blockIdx.x & 3;    // 0..3
    const int m_base = mtile * BM;
    const int n_base = ntile * BN;

    // ---- staging: A 1024 chunks (2/thread), B 2048 chunks (4/thread) ----
    const __half* aG = g_A16 + (size_t)m_base * KDIM;
    const __half* bG = g_Bt + (size_t)n_base * KDIM;

    auto issue = [&](int kt) {
        const uint32_t stage = (uint32_t)(kt & (STAGES - 1)) * STAGE_BYTES;
        const int koff = kt * BK;
#pragma unroll
        for (int i = 0; i < 2; i++) {
            const int c = tid + 512 * i;
            const int row = c >> 3, ch = c & 7;
            const uint32_t dst = smem_base + stage + (uint32_t)row * 128u +
                                 (uint32_t)((ch ^ (row & 7)) * 16);
            CP_ASYNC16(dst, aG + (size_t)row * KDIM + koff + ch * 8);
        }
#pragma unroll
        for (int i = 0; i < 4; i++) {
            const int c = tid + 512 * i;
            const int row = c >> 3, ch = c & 7;
            const uint32_t dst = smem_base + stage + A_STAGE_BYTES +
                                 (uint32_t)row * 128u +
                                 (uint32_t)((ch ^ (row & 7)) * 16);
            CP_ASYNC16(dst, bG + (size_t)row * KDIM + koff + ch * 8);
        }
    };

    // ---- fragment addressing ----
    const int wm = (wid & 1) * 64;    // warp M offset (0/64)
    const int wn = (wid >> 1) * 32;   // warp N offset (0..224)
    // A x4: m0 rows 0-7 k0-7 | m1 rows 8-15 k0-7 | m2 rows 0-7 k8-15 | m3 ...
    const int arF = (lane & 7) + (((lane >> 3) & 1) << 3);
    const uint32_t acp = (uint32_t)(lane >> 4);        // chunk parity
    const uint32_t asw = (uint32_t)(lane & 7);
    uint32_t rowA[4];
#pragma unroll
    for (int mt = 0; mt < 4; mt++)
        rowA[mt] = smem_base + (uint32_t)(wm + 16 * mt + arF) * 128u;
    // B x4: m0 n0-7 k0-7 | m1 n0-7 k8-15 | m2 n8-15 k0-7 | m3 n8-15 k8-15
    const int brF = (lane & 7) + (((lane >> 4) & 1) << 3);
    const uint32_t bcp = (uint32_t)((lane >> 3) & 1);
    const uint32_t bsw = (uint32_t)(lane & 7);
    uint32_t rowB[2];
#pragma unroll
    for (int g = 0; g < 2; g++)
        rowB[g] = smem_base + A_STAGE_BYTES +
                  (uint32_t)(wn + 16 * g + brF) * 128u;

    float acc[4][4][4];
#pragma unroll
    for (int mt = 0; mt < 4; mt++)
#pragma unroll
        for (int nt = 0; nt < 4; nt++)
#pragma unroll
            for (int i = 0; i < 4; i++) acc[mt][nt][i] = 0.0f;

    // ---- prologue ----
#pragma unroll
    for (int p = 0; p < STAGES - 1; p++) {
        issue(p);
        CP_COMMIT();
    }

    // ---- main loop ----
    for (int kt = 0; kt < KITERS; kt++) {
        CP_WAIT(STAGES - 2);
        __syncthreads();

        if (kt + STAGES - 1 < KITERS) issue(kt + STAGES - 1);
        CP_COMMIT();

        const uint32_t stage = (uint32_t)(kt & (STAGES - 1)) * STAGE_BYTES;

#pragma unroll
        for (int ks = 0; ks < 4; ks++) {   // 4 x k16 per ktile
            const uint32_t ak = (((uint32_t)(2 * ks) + acp) ^ asw) * 16u + stage;
            const uint32_t bk = (((uint32_t)(2 * ks) + bcp) ^ bsw) * 16u + stage;

            uint32_t a[4][4];
#pragma unroll
            for (int mt = 0; mt < 4; mt++) LDMX4(a[mt], rowA[mt] + ak);
            uint32_t b[2][4];  // [g]: {b0 t2g, b1 t2g, b0 t2g+1, b1 t2g+1}
#pragma unroll
            for (int g = 0; g < 2; g++) LDMX4(b[g], rowB[g] + bk);

#pragma unroll
            for (int mt = 0; mt < 4; mt++)
#pragma unroll
                for (int nt = 0; nt < 4; nt++)
                    mma_f16(acc[mt][nt], a[mt], &b[nt >> 1][(nt & 1) * 2]);
        }
    }

    // ---- epilogue: mask & scale already folded into A ----
#pragma unroll
    for (int mt = 0; mt < 4; mt++) {
        const int r0 = m_base + wm + 16 * mt + (lane >> 2);
        const int r1 = r0 + 8;
        float* o0 = out + (size_t)r0 * HDIM + n_base + wn + 2 * (lane & 3);
        float* o1 = out + (size_t)r1 * HDIM + n_base + wn + 2 * (lane & 3);
#pragma unroll
        for (int nt = 0; nt < 4; nt++) {
            *reinterpret_cast<float2*>(o0 + nt * 8) =
                make_float2(acc[mt][nt][0], acc[mt][nt][1]);
            *reinterpret_cast<float2*>(o1 + nt * 8) =
                make_float2(acc[mt][nt][2], acc[mt][nt][3]);
        }
    }
}

}  // anonymous namespace

// ---------------------------------------------------------------------------
extern "C" void kernel_launch(void* const* d_in, const int* in_sizes, int n_in,
                              void* d_out, int out_size) {
    const int*   inputs = (const int*)d_in[0];
    const float* W0     = (const float*)d_in[1];
    const float* W1     = (const float*)d_in[2];
    float*       out    = (float*)d_out;
    (void)in_sizes; (void)n_in; (void)out_size;

    cudaFuncSetAttribute(gemm_f16,
                         cudaFuncAttributeMaxDynamicSharedMemorySize,
                         SMEM_TOTAL);

    prep_b<<<dim3(HDIM / 32, KDIM / 32), dim3(32, 8)>>>(W1);
    prep_a<<<TOKENS, 256>>>(inputs, W0);

    const int grid = (TOKENS / BM) * (HDIM / BN);   // 512
    gemm_f16<<<grid, THREADS, SMEM_TOTAL>>>(out);
}

// round 5
// speedup vs baseline: 3.3113x; 1.1859x over previous
#include <cuda_runtime.h>
#include <cuda_fp16.h>
#include <cstdint>

// ============================================================================
// out[16384,1024] = (W0[idx] @ W1) * (idx != 0) * 32.0
//
// Round 5 (compute_100 virtual arch: sm_80 mma path):
//   prep:  one kernel; blocks < TOKENS gather W0 rows -> fp16 A16 with mask
//          and *32 folded in; remaining blocks transpose W1 -> fp16 Bt K-major.
//   gemm:  dense fp16 m16n8k16, CTA tile 128x128, 8 warps (64x32 each),
//          STAGES=3 -> 96KB smem -> 2 CTAs/SM.
//   FIX vs round 4: correct 3-stage ring (consume kt%3, produce (kt+2)%3);
//   the previous hand-rolled rotation skipped a slot each iteration.
// ============================================================================

namespace {

constexpr int TOKENS = 16384;
constexpr int KDIM   = 2048;
constexpr int HDIM   = 1024;

constexpr int BM = 128;
constexpr int BN = 128;
constexpr int BK = 64;              // 64 halfs = 128 B rows
constexpr int STAGES = 3;
constexpr int KITERS = KDIM / BK;   // 32

constexpr int THREADS = 256;        // 8 warps: 2 (M) x 4 (N), warp tile 64x32

constexpr uint32_t A_STAGE_BYTES = BM * 128;                       // 16 KB
constexpr uint32_t B_STAGE_BYTES = BN * 128;                       // 16 KB
constexpr uint32_t STAGE_BYTES   = A_STAGE_BYTES + B_STAGE_BYTES;  // 32 KB
constexpr uint32_t RING_BYTES    = STAGES * STAGE_BYTES;           // 96 KB
constexpr uint32_t SMEM_TOTAL    = RING_BYTES;

constexpr int PREP_B_BLOCKS = (HDIM / 32) * (KDIM / 32);           // 2048

__device__ __half g_A16[(size_t)TOKENS * KDIM];  // gathered, masked, *32
__device__ __half g_Bt[(size_t)HDIM * KDIM];     // W1^T, K-major

// ---------------------------------------------------------------------------
// helpers
// ---------------------------------------------------------------------------
__device__ __forceinline__ uint32_t smem_u32(const void* p) {
    uint32_t a;
    asm("{ .reg .u64 t; cvta.to.shared.u64 t, %1; cvt.u32.u64 %0, t; }"
        : "=r"(a) : "l"(p));
    return a;
}

#define CP_ASYNC16(dst, src) \
    asm volatile("cp.async.cg.shared.global [%0], [%1], 16;" \
                 :: "r"(dst), "l"(src) : "memory")
#define CP_COMMIT() asm volatile("cp.async.commit_group;" ::: "memory")
#define CP_WAIT(n)  asm volatile("cp.async.wait_group %0;" :: "n"(n) : "memory")

#define LDMX4(r, addr)                                                        \
    asm volatile("ldmatrix.sync.aligned.m8n8.x4.shared.b16 {%0,%1,%2,%3}, [%4];" \
        : "=r"((r)[0]), "=r"((r)[1]), "=r"((r)[2]), "=r"((r)[3])              \
        : "r"(addr))

__device__ __forceinline__ void mma_f16(float* d, const uint32_t* a,
                                        const uint32_t* b) {
    asm volatile(
        "mma.sync.aligned.m16n8k16.row.col.f32.f16.f16.f32 "
        "{%0,%1,%2,%3}, {%4,%5,%6,%7}, {%8,%9}, {%0,%1,%2,%3};"
        : "+f"(d[0]), "+f"(d[1]), "+f"(d[2]), "+f"(d[3])
        : "r"(a[0]), "r"(a[1]), "r"(a[2]), "r"(a[3]), "r"(b[0]), "r"(b[1]));
}

// ---------------------------------------------------------------------------
// prep: gather/convert A (blocks 0..TOKENS-1) + transpose W1 (the rest)
// ---------------------------------------------------------------------------
__global__ __launch_bounds__(256)
void prep(const int* __restrict__ inputs, const float* __restrict__ W0,
          const float* __restrict__ W1) {
    __shared__ float tile[32][33];
    const int bid = blockIdx.x;
    const int tid = threadIdx.x;

    if (bid < TOKENS) {
        const int tok = inputs[bid];
        const float sc = (tok != 0) ? 32.0f : 0.0f;
        const float4* src =
            reinterpret_cast<const float4*>(W0 + (size_t)tok * KDIM);
        uint2* dst = reinterpret_cast<uint2*>(g_A16 + (size_t)bid * KDIM);
#pragma unroll 2
        for (int i = tid; i < KDIM / 4; i += 256) {
            float4 v = src[i];
            __half2 h0 = __floats2half2_rn(v.x * sc, v.y * sc);
            __half2 h1 = __floats2half2_rn(v.z * sc, v.w * sc);
            uint2 u;
            u.x = *reinterpret_cast<uint32_t*>(&h0);
            u.y = *reinterpret_cast<uint32_t*>(&h1);
            dst[i] = u;
        }
    } else {
        const int bid2 = bid - TOKENS;
        const int n0 = (bid2 & 31) * 32;
        const int k0 = (bid2 >> 5) * 32;
        const int tx = tid & 31;
        const int tyb = tid >> 5;
#pragma unroll
        for (int dy = 0; dy < 32; dy += 8) {
            int ty = tyb + dy;
            tile[ty][tx] = W1[(size_t)(k0 + ty) * HDIM + n0 + tx];
        }
        __syncthreads();
#pragma unroll
        for (int dy = 0; dy < 32; dy += 8) {
            int ty = tyb + dy;
            g_Bt[(size_t)(n0 + ty) * KDIM + k0 + tx] =
                __float2half_rn(tile[tx][ty]);
        }
    }
}

// ---------------------------------------------------------------------------
// main dense fp16 GEMM: out[16384,1024] = A16 @ Bt^T   (fp32 accumulate)
// ---------------------------------------------------------------------------
__global__ __launch_bounds__(THREADS, 2)
void gemm_f16(float* __restrict__ out) {
    extern __shared__ char smem[];
    const uint32_t smem_base = smem_u32(smem);

    const int tid  = threadIdx.x;
    const int lane = tid & 31;
    const int wid  = tid >> 5;

    const int mtile  = blockIdx.x >> 3;   // 0..127
    const int ntile  = blockIdx.x & 7;    // 0..7
    const int m_base = mtile * BM;
    const int n_base = ntile * BN;

    const __half* aG = g_A16 + (size_t)m_base * KDIM;
    const __half* bG = g_Bt + (size_t)n_base * KDIM;

    // stage issue: A 1024 chunks (4/thread), B 1024 chunks (4/thread)
    auto issue = [&](int kt, uint32_t stage) {
        const int koff = kt * BK;
#pragma unroll
        for (int i = 0; i < 4; i++) {
            const int c = tid + 256 * i;
            const int row = c >> 3, ch = c & 7;
            const uint32_t dst = smem_base + stage + (uint32_t)row * 128u +
                                 (uint32_t)((ch ^ (row & 7)) * 16);
            CP_ASYNC16(dst, aG + (size_t)row * KDIM + koff + ch * 8);
        }
#pragma unroll
        for (int i = 0; i < 4; i++) {
            const int c = tid + 256 * i;
            const int row = c >> 3, ch = c & 7;
            const uint32_t dst = smem_base + stage + A_STAGE_BYTES +
                                 (uint32_t)row * 128u +
                                 (uint32_t)((ch ^ (row & 7)) * 16);
            CP_ASYNC16(dst, bG + (size_t)row * KDIM + koff + ch * 8);
        }
    };

    // ---- fragment addressing ----
    const int wm = (wid & 1) * 64;    // warp M offset (0/64)
    const int wn = (wid >> 1) * 32;   // warp N offset (0/32/64/96)
    const int arF = (lane & 7) + (((lane >> 3) & 1) << 3);
    const uint32_t acp = (uint32_t)(lane >> 4);
    const uint32_t asw = (uint32_t)(lane & 7);
    uint32_t rowA[4];
#pragma unroll
    for (int mt = 0; mt < 4; mt++)
        rowA[mt] = smem_base + (uint32_t)(wm + 16 * mt + arF) * 128u;
    const int brF = (lane & 7) + (((lane >> 4) & 1) << 3);
    const uint32_t bcp = (uint32_t)((lane >> 3) & 1);
    const uint32_t bsw = (uint32_t)(lane & 7);
    uint32_t rowB[2];
#pragma unroll
    for (int g = 0; g < 2; g++)
        rowB[g] = smem_base + A_STAGE_BYTES +
                  (uint32_t)(wn + 16 * g + brF) * 128u;

    float acc[4][4][4];
#pragma unroll
    for (int mt = 0; mt < 4; mt++)
#pragma unroll
        for (int nt = 0; nt < 4; nt++)
#pragma unroll
            for (int i = 0; i < 4; i++) acc[mt][nt][i] = 0.0f;

    // ---- prologue: kt=0 -> slot0, kt=1 -> slot1 ----
    issue(0, 0);
    CP_COMMIT();
    issue(1, STAGE_BYTES);
    CP_COMMIT();

    // ---- main loop: consume slot kt%3, produce kt+2 into slot (kt+2)%3 ----
    uint32_t s_cons = 0;                  // slot of kt
    uint32_t s_prod = 2 * STAGE_BYTES;    // slot of kt+2
    for (int kt = 0; kt < KITERS; kt++) {
        CP_WAIT(1);
        __syncthreads();

        if (kt + 2 < KITERS) issue(kt + 2, s_prod);
        CP_COMMIT();

        const uint32_t stage = s_cons;
        s_cons += STAGE_BYTES; if (s_cons == RING_BYTES) s_cons = 0;
        s_prod += STAGE_BYTES; if (s_prod == RING_BYTES) s_prod = 0;

#pragma unroll
        for (int ks = 0; ks < 4; ks++) {   // 4 x k16 per ktile
            const uint32_t ak = (((uint32_t)(2 * ks) + acp) ^ asw) * 16u + stage;
            const uint32_t bk = (((uint32_t)(2 * ks) + bcp) ^ bsw) * 16u + stage;

            uint32_t a[4][4];
#pragma unroll
            for (int mt = 0; mt < 4; mt++) LDMX4(a[mt], rowA[mt] + ak);
            uint32_t b[2][4];
#pragma unroll
            for (int g = 0; g < 2; g++) LDMX4(b[g], rowB[g] + bk);

#pragma unroll
            for (int mt = 0; mt < 4; mt++)
#pragma unroll
                for (int nt = 0; nt < 4; nt++)
                    mma_f16(acc[mt][nt], a[mt], &b[nt >> 1][(nt & 1) * 2]);
        }
    }

    // ---- epilogue: mask & scale already folded into A ----
#pragma unroll
    for (int mt = 0; mt < 4; mt++) {
        const int r0 = m_base + wm + 16 * mt + (lane >> 2);
        const int r1 = r0 + 8;
        float* o0 = out + (size_t)r0 * HDIM + n_base + wn + 2 * (lane & 3);
        float* o1 = out + (size_t)r1 * HDIM + n_base + wn + 2 * (lane & 3);
#pragma unroll
        for (int nt = 0; nt < 4; nt++) {
            *reinterpret_cast<float2*>(o0 + nt * 8) =
                make_float2(acc[mt][nt][0], acc[mt][nt][1]);
            *reinterpret_cast<float2*>(o1 + nt * 8) =
                make_float2(acc[mt][nt][2], acc[mt][nt][3]);
        }
    }
}

}  // anonymous namespace

// ---------------------------------------------------------------------------
extern "C" void kernel_launch(void* const* d_in, const int* in_sizes, int n_in,
                              void* d_out, int out_size) {
    const int*   inputs = (const int*)d_in[0];
    const float* W0     = (const float*)d_in[1];
    const float* W1     = (const float*)d_in[2];
    float*       out    = (float*)d_out;
    (void)in_sizes; (void)n_in; (void)out_size;

    cudaFuncSetAttribute(gemm_f16,
                         cudaFuncAttributeMaxDynamicSharedMemorySize,
                         SMEM_TOTAL);

    prep<<<TOKENS + PREP_B_BLOCKS, 256>>>(inputs, W0, W1);

    const int grid = (TOKENS / BM) * (HDIM / BN);   // 128 * 8 = 1024
    gemm_f16<<<grid, THREADS, SMEM_TOTAL>>>(out);
}

// round 6
// speedup vs baseline: 3.4965x; 1.0559x over previous
#include <cuda_runtime.h>
#include <cuda_fp16.h>
#include <cstdint>

// ============================================================================
// out[16384,1024] = (W0[idx] @ W1) * (idx != 0) * 32.0
//
// Round 6 (compute_100 virtual arch: sm_80 mma path):
//   prep: blocks < TOKENS gather W0 rows -> fp16 A16 (mask & *32 folded),
//         one uint4 store per thread; remaining blocks transpose W1 -> Bt.
//   gemm: dense fp16 m16n8k16, CTA 128x128, 8 warps (64x32), STAGES=3,
//         96KB smem, 126 regs -> 2 CTAs/SM (register wall at 64K regs).
//         kt-loop unrolled by ring period 3 (constant stage offsets);
//         inner ks loads B frags first, then per-mt A frag + its 4 MMAs.
// ============================================================================

namespace {

constexpr int TOKENS = 16384;
constexpr int KDIM   = 2048;
constexpr int HDIM   = 1024;

constexpr int BM = 128;
constexpr int BN = 128;
constexpr int BK = 64;              // 64 halfs = 128 B rows
constexpr int KITERS = KDIM / BK;   // 32

constexpr int THREADS = 256;        // 8 warps: 2 (M) x 4 (N), warp tile 64x32

constexpr uint32_t A_STAGE_BYTES = BM * 128;                       // 16 KB
constexpr uint32_t B_STAGE_BYTES = BN * 128;                       // 16 KB
constexpr uint32_t STAGE_BYTES   = A_STAGE_BYTES + B_STAGE_BYTES;  // 32 KB
constexpr uint32_t SMEM_TOTAL    = 3 * STAGE_BYTES;                // 96 KB

constexpr int PREP_B_BLOCKS = (HDIM / 32) * (KDIM / 32);           // 2048

__device__ __half g_A16[(size_t)TOKENS * KDIM];  // gathered, masked, *32
__device__ __half g_Bt[(size_t)HDIM * KDIM];     // W1^T, K-major

// ---------------------------------------------------------------------------
// helpers
// ---------------------------------------------------------------------------
__device__ __forceinline__ uint32_t smem_u32(const void* p) {
    uint32_t a;
    asm("{ .reg .u64 t; cvta.to.shared.u64 t, %1; cvt.u32.u64 %0, t; }"
        : "=r"(a) : "l"(p));
    return a;
}

#define CP_ASYNC16(dst, src) \
    asm volatile("cp.async.cg.shared.global [%0], [%1], 16;" \
                 :: "r"(dst), "l"(src) : "memory")
#define CP_COMMIT() asm volatile("cp.async.commit_group;" ::: "memory")
#define CP_WAIT(n)  asm volatile("cp.async.wait_group %0;" :: "n"(n) : "memory")

#define LDMX4(r, addr)                                                        \
    asm volatile("ldmatrix.sync.aligned.m8n8.x4.shared.b16 {%0,%1,%2,%3}, [%4];" \
        : "=r"((r)[0]), "=r"((r)[1]), "=r"((r)[2]), "=r"((r)[3])              \
        : "r"(addr))

__device__ __forceinline__ void mma_f16(float* d, const uint32_t* a,
                                        const uint32_t* b) {
    asm volatile(
        "mma.sync.aligned.m16n8k16.row.col.f32.f16.f16.f32 "
        "{%0,%1,%2,%3}, {%4,%5,%6,%7}, {%8,%9}, {%0,%1,%2,%3};"
        : "+f"(d[0]), "+f"(d[1]), "+f"(d[2]), "+f"(d[3])
        : "r"(a[0]), "r"(a[1]), "r"(a[2]), "r"(a[3]), "r"(b[0]), "r"(b[1]));
}

// ---------------------------------------------------------------------------
// prep: gather/convert A (blocks 0..TOKENS-1) + transpose W1 (the rest)
// ---------------------------------------------------------------------------
__global__ __launch_bounds__(256)
void prep(const int* __restrict__ inputs, const float* __restrict__ W0,
          const float* __restrict__ W1) {
    __shared__ float tile[32][33];
    const int bid = blockIdx.x;
    const int tid = threadIdx.x;

    if (bid < TOKENS) {
        const int tok = inputs[bid];
        const float sc = (tok != 0) ? 32.0f : 0.0f;
        const float4* src =
            reinterpret_cast<const float4*>(W0 + (size_t)tok * KDIM);
        uint4* dst = reinterpret_cast<uint4*>(g_A16 + (size_t)bid * KDIM);
        // KDIM/8 = 256 uint4 chunks, exactly one per thread
        float4 v0 = src[2 * tid];
        float4 v1 = src[2 * tid + 1];
        __half2 h0 = __floats2half2_rn(v0.x * sc, v0.y * sc);
        __half2 h1 = __floats2half2_rn(v0.z * sc, v0.w * sc);
        __half2 h2 = __floats2half2_rn(v1.x * sc, v1.y * sc);
        __half2 h3 = __floats2half2_rn(v1.z * sc, v1.w * sc);
        uint4 u;
        u.x = *reinterpret_cast<uint32_t*>(&h0);
        u.y = *reinterpret_cast<uint32_t*>(&h1);
        u.z = *reinterpret_cast<uint32_t*>(&h2);
        u.w = *reinterpret_cast<uint32_t*>(&h3);
        dst[tid] = u;
    } else {
        const int bid2 = bid - TOKENS;
        const int n0 = (bid2 & 31) * 32;
        const int k0 = (bid2 >> 5) * 32;
        const int tx = tid & 31;
        const int tyb = tid >> 5;
#pragma unroll
        for (int dy = 0; dy < 32; dy += 8) {
            int ty = tyb + dy;
            tile[ty][tx] = W1[(size_t)(k0 + ty) * HDIM + n0 + tx];
        }
        __syncthreads();
#pragma unroll
        for (int dy = 0; dy < 32; dy += 8) {
            int ty = tyb + dy;
            g_Bt[(size_t)(n0 + ty) * KDIM + k0 + tx] =
                __float2half_rn(tile[tx][ty]);
        }
    }
}

// ---------------------------------------------------------------------------
// main dense fp16 GEMM: out[16384,1024] = A16 @ Bt^T   (fp32 accumulate)
// ---------------------------------------------------------------------------
__global__ __launch_bounds__(THREADS, 2)
void gemm_f16(float* __restrict__ out) {
    extern __shared__ char smem[];
    const uint32_t smem_base = smem_u32(smem);

    const int tid  = threadIdx.x;
    const int lane = tid & 31;
    const int wid  = tid >> 5;

    const int mtile  = blockIdx.x >> 3;   // 0..127
    const int ntile  = blockIdx.x & 7;    // 0..7
    const int m_base = mtile * BM;
    const int n_base = ntile * BN;

    const __half* aG = g_A16 + (size_t)m_base * KDIM;
    const __half* bG = g_Bt + (size_t)n_base * KDIM;

    // stage issue: A 1024 chunks (4/thread), B 1024 chunks (4/thread)
    auto issue = [&](int kt, uint32_t stage) {
        const int koff = kt * BK;
#pragma unroll
        for (int i = 0; i < 4; i++) {
            const int c = tid + 256 * i;
            const int row = c >> 3, ch = c & 7;
            const uint32_t dst = smem_base + stage + (uint32_t)row * 128u +
                                 (uint32_t)((ch ^ (row & 7)) * 16);
            CP_ASYNC16(dst, aG + (size_t)row * KDIM + koff + ch * 8);
        }
#pragma unroll
        for (int i = 0; i < 4; i++) {
            const int c = tid + 256 * i;
            const int row = c >> 3, ch = c & 7;
            const uint32_t dst = smem_base + stage + A_STAGE_BYTES +
                                 (uint32_t)row * 128u +
                                 (uint32_t)((ch ^ (row & 7)) * 16);
            CP_ASYNC16(dst, bG + (size_t)row * KDIM + koff + ch * 8);
        }
    };

    // ---- fragment addressing ----
    const int wm = (wid & 1) * 64;    // warp M offset (0/64)
    const int wn = (wid >> 1) * 32;   // warp N offset (0/32/64/96)
    const int arF = (lane & 7) + (((lane >> 3) & 1) << 3);
    const uint32_t acp = (uint32_t)(lane >> 4);
    const uint32_t asw = (uint32_t)(lane & 7);
    uint32_t rowA[4];
#pragma unroll
    for (int mt = 0; mt < 4; mt++)
        rowA[mt] = smem_base + (uint32_t)(wm + 16 * mt + arF) * 128u;
    const int brF = (lane & 7) + (((lane >> 4) & 1) << 3);
    const uint32_t bcp = (uint32_t)((lane >> 3) & 1);
    const uint32_t bsw = (uint32_t)(lane & 7);
    uint32_t rowB[2];
#pragma unroll
    for (int g = 0; g < 2; g++)
        rowB[g] = smem_base + A_STAGE_BYTES +
                  (uint32_t)(wn + 16 * g + brF) * 128u;

    float acc[4][4][4];
#pragma unroll
    for (int mt = 0; mt < 4; mt++)
#pragma unroll
        for (int nt = 0; nt < 4; nt++)
#pragma unroll
            for (int i = 0; i < 4; i++) acc[mt][nt][i] = 0.0f;

    // ---- prologue: kt=0 -> slot0, kt=1 -> slot1 ----
    issue(0, 0);
    CP_COMMIT();
    issue(1, STAGE_BYTES);
    CP_COMMIT();

    // one pipeline step: consume kt from `stage`, produce kt+2 into `prod`
    auto body = [&](int kt, uint32_t stage, uint32_t prod) {
        CP_WAIT(1);
        __syncthreads();

        if (kt + 2 < KITERS) issue(kt + 2, prod);
        CP_COMMIT();

#pragma unroll
        for (int ks = 0; ks < 4; ks++) {   // 4 x k16 per ktile
            const uint32_t ak = (((uint32_t)(2 * ks) + acp) ^ asw) * 16u + stage;
            const uint32_t bk = (((uint32_t)(2 * ks) + bcp) ^ bsw) * 16u + stage;

            // B fragments first (2 LDSM), then per-mt A frag + its 4 MMAs
            uint32_t b[2][4];
#pragma unroll
            for (int g = 0; g < 2; g++) LDMX4(b[g], rowB[g] + bk);
#pragma unroll
            for (int mt = 0; mt < 4; mt++) {
                uint32_t a[4];
                LDMX4(a, rowA[mt] + ak);
#pragma unroll
                for (int nt = 0; nt < 4; nt++)
                    mma_f16(acc[mt][nt], a, &b[nt >> 1][(nt & 1) * 2]);
            }
        }
    };

    // ---- main loop: ring period 3, compile-time stage offsets ----
    constexpr uint32_t S0 = 0, S1 = STAGE_BYTES, S2 = 2 * STAGE_BYTES;
    for (int base = 0; base < 30; base += 3) {
        body(base + 0, S0, S2);
        body(base + 1, S1, S0);
        body(base + 2, S2, S1);
    }
    body(30, S0, S2);   // kt=30 (30%3=0), no issue (32 >= KITERS)
    body(31, S1, S0);   // kt=31 (31%3=1), no issue

    // ---- epilogue: mask & scale already folded into A ----
#pragma unroll
    for (int mt = 0; mt < 4; mt++) {
        const int r0 = m_base + wm + 16 * mt + (lane >> 2);
        const int r1 = r0 + 8;
        float* o0 = out + (size_t)r0 * HDIM + n_base + wn + 2 * (lane & 3);
        float* o1 = out + (size_t)r1 * HDIM + n_base + wn + 2 * (lane & 3);
#pragma unroll
        for (int nt = 0; nt < 4; nt++) {
            *reinterpret_cast<float2*>(o0 + nt * 8) =
                make_float2(acc[mt][nt][0], acc[mt][nt][1]);
            *reinterpret_cast<float2*>(o1 + nt * 8) =
                make_float2(acc[mt][nt][2], acc[mt][nt][3]);
        }
    }
}

}  // anonymous namespace

// ---------------------------------------------------------------------------
extern "C" void kernel_launch(void* const* d_in, const int* in_sizes, int n_in,
                              void* d_out, int out_size) {
    const int*   inputs = (const int*)d_in[0];
    const float* W0     = (const float*)d_in[1];
    const float* W1     = (const float*)d_in[2];
    float*       out    = (float*)d_out;
    (void)in_sizes; (void)n_in; (void)out_size;

    cudaFuncSetAttribute(gemm_f16,
                         cudaFuncAttributeMaxDynamicSharedMemorySize,
                         SMEM_TOTAL);

    prep<<<TOKENS + PREP_B_BLOCKS, 256>>>(inputs, W0, W1);

    const int grid = (TOKENS / BM) * (HDIM / BN);   // 128 * 8 = 1024
    gemm_f16<<<grid, THREADS, SMEM_TOTAL>>>(out);
}